// round 16
// baseline (speedup 1.0000x reference)
#include <cuda_runtime.h>
#include <cuda_fp16.h>
#include <cstdint>

#define H   128
#define W   256
#define HW  32768
#define FH  128
#define XPH 130
#define XPW 258
#define PLANE (XPH*XPW*32)

// ---------------- scratch (device globals; no allocation allowed) ----------------
__device__ __half g_xm_h[8*PLANE];   // m, padded NHWC (2x 32ch planes per batch), fp16
__device__ __half g_xa_h[8*PLANE];   // aux, same layout
__device__ __half g_wt2[6*4*2048];   // Winograd weights [chunk(icc,ky)][tap4][oc64][ic32]
__device__ int   g_geo[HW];
__device__ float g_dx[HW];
__device__ float g_dy[HW];

// ---------------- helpers ----------------
__device__ __forceinline__ uint32_t smem_u32(const void* p) {
    uint32_t a;
    asm("{ .reg .u64 t; cvta.to.shared.u64 t, %1; cvt.u32.u64 %0, t; }" : "=r"(a) : "l"(p));
    return a;
}
__device__ __forceinline__ uint32_t h2u(__half2 h) {
    return *reinterpret_cast<uint32_t*>(&h);
}
__device__ __forceinline__ void cp16(uint32_t dst, const void* src) {
    unsigned long long g = (unsigned long long)__cvta_generic_to_global(src);
    asm volatile("cp.async.cg.shared.global [%0], [%1], 16;" :: "r"(dst), "l"(g) : "memory");
}
__device__ __forceinline__ void ldm4(uint32_t* r, uint32_t addr) {
    asm volatile("ldmatrix.sync.aligned.m8n8.x4.shared.b16 {%0,%1,%2,%3}, [%4];"
        : "=r"(r[0]), "=r"(r[1]), "=r"(r[2]), "=r"(r[3]) : "r"(addr));
}
__device__ __forceinline__ void mma16(float* d, const uint32_t* a, const uint32_t* b) {
    asm volatile(
        "mma.sync.aligned.m16n8k16.row.col.f32.f16.f16.f32 "
        "{%0,%1,%2,%3}, {%4,%5,%6,%7}, {%8,%9}, {%0,%1,%2,%3};"
        : "+f"(d[0]), "+f"(d[1]), "+f"(d[2]), "+f"(d[3])
        : "r"(a[0]), "r"(a[1]), "r"(a[2]), "r"(a[3]), "r"(b[0]), "r"(b[1]));
}
__device__ __forceinline__ uint4 hadd8(uint4 a, uint4 b) {
    uint4 r;
    r.x = h2u(__hadd2(*(__half2*)&a.x, *(__half2*)&b.x));
    r.y = h2u(__hadd2(*(__half2*)&a.y, *(__half2*)&b.y));
    r.z = h2u(__hadd2(*(__half2*)&a.z, *(__half2*)&b.z));
    r.w = h2u(__hadd2(*(__half2*)&a.w, *(__half2*)&b.w));
    return r;
}
__device__ __forceinline__ uint4 hsub8(uint4 a, uint4 b) {
    uint4 r;
    r.x = h2u(__hsub2(*(__half2*)&a.x, *(__half2*)&b.x));
    r.y = h2u(__hsub2(*(__half2*)&a.y, *(__half2*)&b.y));
    r.z = h2u(__hsub2(*(__half2*)&a.z, *(__half2*)&b.z));
    r.w = h2u(__hsub2(*(__half2*)&a.w, *(__half2*)&b.w));
    return r;
}

// ---------------- 1) merged prologue: geom | pad | Winograd wtprep ----------------
__global__ __launch_bounds__(256) void prologue_kernel(const float* __restrict__ wf) {
    int t = blockIdx.x * 256 + threadIdx.x;
    if (t < 32768) {
        int p = t;
        int i = p >> 8;
        int j = p & 255;
        const float PI = 3.14159265358979323846f;
        float lat = (0.5f - (i + 0.5f) / 128.f) * PI;
        float lon = (2.f * (j + 0.5f) / 256.f - 1.f) * PI;
        float cl = cosf(lat);
        float vx = cl * sinf(lon);
        float vy = sinf(lat);
        float vz = cl * cosf(lon);
        float ax = fabsf(vx), ay = fabsf(vy), az = fabsf(vz);
        bool cond_z = (az >= ax) && (az >= ay);
        bool cond_x = (!cond_z) && (ax >= ay);
        int face;
        if (cond_z)      face = (vz > 0.f) ? 2 : 0;
        else if (cond_x) face = (vx > 0.f) ? 4 : 3;
        else             face = (vy > 0.f) ? 5 : 1;
        float den, a, bc;
        switch (face) {
            case 0: den = -vz; a = -vx / den; bc =  vy / den; break;
            case 1: den = -vy; a =  vx / den; bc = -vz / den; break;
            case 2: den =  vz; a =  vx / den; bc =  vy / den; break;
            case 3: den = -vx; a =  vz / den; bc =  vy / den; break;
            case 4: den =  vx; a = -vz / den; bc =  vy / den; break;
            default:den =  vy; a =  vx / den; bc =  vz / den; break;
        }
        float uu = fminf(fmaxf((a   + 1.f) * 0.5f * 127.f, 0.f), 127.f);
        float vv = fminf(fmaxf((1.f - bc ) * 0.5f * 127.f, 0.f), 127.f);
        int x0 = (int)floorf(uu);
        int y0 = (int)floorf(vv);
        int x1 = min(x0 + 1, 127);
        int y1 = min(y0 + 1, 127);
        g_geo[p] = face | (x0 << 3) | (y0 << 10) | (x1 << 17) | (y1 << 24);
        g_dx[p] = uu - (float)x0;
        g_dy[p] = vv - (float)y0;
    } else if (t < 230400) {
        const int PER2 = 12352;
        int tt = t - 32768;
        __half* base = (tt < 8 * PER2) ? g_xm_h : g_xa_h;
        int r = tt % (8 * PER2);
        int plane = r / PER2;
        int e = r % PER2;
        int y, x, ic2;
        if (e < 8256) {
            y = (e < 4128) ? 0 : 129;
            int o = e % 4128; x = o >> 4; ic2 = o & 15;
        } else {
            int e2 = e - 8256;
            x = (e2 < 2048) ? 0 : 257;
            int o = e2 & 2047; y = 1 + (o >> 4); ic2 = o & 15;
        }
        *(uint32_t*)(base + ((size_t)(plane * XPH + y) * XPW + x) * 32 + ic2 * 2) = 0u;
    } else if (t < 279552) {
        int idx = t - 230400;                    // 6*4*2048 items
        int ch = idx / 8192;                     // icc*3 + ky
        int r  = idx % 8192;
        int tap = r >> 11;
        int oc = (r >> 5) & 63;
        int ic = r & 31;
        int icc = ch / 3, ky = ch % 3;
        const float* wb = wf + (oc * 64 + icc * 32 + ic) * 9 + ky * 3;
        float w0 = wb[0], w1 = wb[1], w2 = wb[2];
        float g;
        switch (tap) {
            case 0: g = w0; break;
            case 1: g = 0.5f * (w0 + w1 + w2); break;
            case 2: g = 0.5f * (w0 - w1 + w2); break;
            default: g = w2; break;
        }
        g_wt2[idx] = __float2half(g);
    }
}

// ---------------- 2) m: NCHW -> padded NHWC fp16 ----------------
__global__ __launch_bounds__(256) void nchw2xp_kernel(const float* __restrict__ m) {
    __shared__ float sm[64][33];
    int blk = blockIdx.x;                        // b*1024 + y*8 + xt
    int xt = blk & 7, y = (blk >> 3) & 127, b = blk >> 10;
    int tid = threadIdx.x;
    int xl = tid & 31, cw = tid >> 5;
    #pragma unroll
    for (int k = 0; k < 8; k++) {
        int c = cw + k * 8;
        sm[c][xl] = m[(((size_t)(b * 64 + c)) * 128 + y) * 256 + xt * 32 + xl];
    }
    __syncthreads();
    #pragma unroll
    for (int k = 0; k < 2; k++) {
        int j = tid + k * 256;
        int px = j >> 4, c0 = (j & 15) * 4, icc = c0 >> 5;
        uint2 pk = make_uint2(h2u(__floats2half2_rn(sm[c0][px],     sm[c0 + 1][px])),
                              h2u(__floats2half2_rn(sm[c0 + 2][px], sm[c0 + 3][px])));
        *(uint2*)(g_xm_h + (((size_t)((b * 2 + icc) * XPH) + y + 1) * XPW + xt * 32 + px + 1) * 32
                  + (c0 & 31)) = pk;
    }
}

// ---------------- 3) bilinear cube gather -> padded NHWC aux fp16 ----------------
__global__ __launch_bounds__(256) void gather_kernel(
    const float* __restrict__ fb, const float* __restrict__ fd,
    const float* __restrict__ ff, const float* __restrict__ fl,
    const float* __restrict__ fr, const float* __restrict__ fu)
{
    __shared__ float sm[64][33];
    int blk = blockIdx.x;
    int xt = blk & 7, y = (blk >> 3) & 127, b = blk >> 10;
    int tid = threadIdx.x;
    int xl = tid & 31, cw = tid >> 5;
    int p = y * 256 + xt * 32 + xl;
    int geo = g_geo[p];
    int face = geo & 7;
    int x0 = (geo >> 3) & 127, y0 = (geo >> 10) & 127;
    int x1 = (geo >> 17) & 127, y1 = (geo >> 24) & 127;
    float dx = g_dx[p], dy = g_dy[p];
    float w00 = (1.f - dx) * (1.f - dy), w01 = dx * (1.f - dy);
    float w10 = (1.f - dx) * dy,         w11 = dx * dy;
    const float* fp0;
    switch (face) {
        case 0: fp0 = fb; break; case 1: fp0 = fd; break; case 2: fp0 = ff; break;
        case 3: fp0 = fl; break; case 4: fp0 = fr; break; default: fp0 = fu; break;
    }
    #pragma unroll
    for (int k = 0; k < 8; k++) {
        int c = cw + k * 8;
        const float* fp = fp0 + ((size_t)(b * 64 + c)) * (FH * FH);
        sm[c][xl] = fp[y0 * FH + x0] * w00 + fp[y0 * FH + x1] * w01
                  + fp[y1 * FH + x0] * w10 + fp[y1 * FH + x1] * w11;
    }
    __syncthreads();
    #pragma unroll
    for (int k = 0; k < 2; k++) {
        int j = tid + k * 256;
        int px = j >> 4, c0 = (j & 15) * 4, icc = c0 >> 5;
        uint2 pk = make_uint2(h2u(__floats2half2_rn(sm[c0][px],     sm[c0 + 1][px])),
                              h2u(__floats2half2_rn(sm[c0 + 2][px], sm[c0 + 3][px])));
        *(uint2*)(g_xa_h + (((size_t)((b * 2 + icc) * XPH) + y + 1) * XPW + xt * 32 + px + 1) * 32
                  + (c0 & 31)) = pk;
    }
}

// ---------------- 4) fused: Winograd F(2,3)-x convs + mask + blend (quarter-row) ----------------
// CTA = 64 out px (32 pairs); 256 threads, 8 warps = 2 M-grp(16 pairs) x 4 N-grp(16 oc).
// smem bytes:
//   [0, 40960)       wt bufs : 2 stages x 4 taps x 64 oc x 80B (20480/stage)
//   [40960, 62080)   raw rows: 2 stages x 2 convs x 66 px x 80B (10560/stage, 5280/conv)
//   [62080, 82560)   T planes: 2 convs x 4 taps x 32 pairs x 80B (single buf)
//   [82560, ...)     bias 64f | wm 128f | bm | maskS 64f | psum 4x64 f
//   epilogue reuse: stage [64][65] f32 at 40960
#define SB_WT  0
#define SB_RAW 40960
#define SB_T   62080
#define SB_PAR 82560
#define SMEMB  84640

__global__ __launch_bounds__(256) void fused_kernel(
    const float* __restrict__ m_in, const float* __restrict__ bfu,
    const float* __restrict__ wm,   const float* __restrict__ bm,
    float* __restrict__ out)
{
    extern __shared__ char smc[];
    const uint32_t sb = smem_u32(smc);
    const int tid = threadIdx.x;
    const int wid = tid >> 5;
    const int lane = tid & 31;
    const int r4 = lane >> 2, c4 = lane & 3;
    const int mq = lane >> 3, r8 = lane & 7;
    const int mg = wid & 1, ng = wid >> 1;       // 2 M-groups, 4 N-groups
    const int q = blockIdx.x & 3;
    const int y = (blockIdx.x >> 2) & 127;
    const int b = blockIdx.x >> 9;
    const int hp = q * 64;                       // padded-col base of this quarter-row

    float* sbias = (float*)(smc + SB_PAR);
    float* swm   = (float*)(smc + SB_PAR + 256);
    float* sbm   = (float*)(smc + SB_PAR + 768);
    float* maskS = (float*)(smc + SB_PAR + 784);
    float* psum  = (float*)(smc + SB_PAR + 1040);
    if (tid < 64)  sbias[tid] = bfu[tid];
    if (tid < 128) swm[tid]   = wm[tid];
    if (tid == 0)  sbm[0]     = bm[0];

    float acc[2][4][2][4];                       // [conv][tap][nt][frag]
    #pragma unroll
    for (int v = 0; v < 2; v++)
        #pragma unroll
        for (int t = 0; t < 4; t++)
            #pragma unroll
            for (int nt = 0; nt < 2; nt++)
                #pragma unroll
                for (int e = 0; e < 4; e++) acc[v][t][nt][e] = 0.f;

    // fill stage s: raw rows (528 cp16) + Winograd weights (1024 cp16)
    auto fill = [&](int s) {
        int icc = s / 3, ky = s % 3;
        size_t rowoff = ((size_t)((b * 2 + icc) * XPH + y + ky)) * XPW * 32;
        const __half* rm = g_xm_h + rowoff;
        const __half* ra = g_xa_h + rowoff;
        uint32_t rdst = sb + SB_RAW + (s & 1) * 10560;
        uint32_t wdst = sb + SB_WT + (s & 1) * 20480;
        const __half* wsrc = g_wt2 + (size_t)(icc * 3 + ky) * 8192;
        #pragma unroll
        for (int i = 0; i < 7; i++) {
            int j = tid + i * 256;
            if (j < 528) {
                int slab = (j >= 264);
                int jj = j - slab * 264;
                int px = jj >> 2, qx = jj & 3;   // px 0..65
                cp16(rdst + slab * 5280 + px * 80 + qx * 16,
                     (slab ? ra : rm) + (hp + px) * 32 + qx * 8);
            } else if (j < 1552) {
                int jj = j - 528;                // tap*256 + oc*4 + q
                int tap = jj >> 8, rr = jj & 255;
                int oc = rr >> 2, qx = rr & 3;
                cp16(wdst + tap * 5120 + oc * 80 + qx * 16,
                     wsrc + tap * 2048 + oc * 32 + qx * 8);
            }
        }
    };

    fill(0);
    asm volatile("cp.async.commit_group;" ::: "memory");

    for (int s = 0; s < 6; s++) {
        __syncthreads();                         // MMA+transform reads of s-1 done
        if (s < 5) {
            fill(s + 1);
            asm volatile("cp.async.commit_group;" ::: "memory");
            asm volatile("cp.async.wait_group 1;" ::: "memory");
        } else {
            asm volatile("cp.async.wait_group 0;" ::: "memory");
        }
        __syncthreads();                         // raw(s)+wt(s) visible

        // ---- input transform: raw -> 4 tap planes per conv (256 items, 1/thread) ----
        {
            int v = tid >> 7, j = (tid >> 2) & 31, cq = tid & 3;
            uint32_t src = SB_RAW + (s & 1) * 10560 + v * 5280 + j * 160 + cq * 16;
            uint4 d0 = *(const uint4*)(smc + src);
            uint4 d1 = *(const uint4*)(smc + src + 80);
            uint4 d2 = *(const uint4*)(smc + src + 160);
            uint4 d3 = *(const uint4*)(smc + src + 240);
            uint32_t dst = SB_T + v * 10240 + j * 80 + cq * 16;
            *(uint4*)(smc + dst)        = hsub8(d0, d2);   // t0
            *(uint4*)(smc + dst + 2560) = hadd8(d1, d2);   // t1
            *(uint4*)(smc + dst + 5120) = hsub8(d2, d1);   // t2
            *(uint4*)(smc + dst + 7680) = hsub8(d1, d3);   // t3
        }
        __syncthreads();                         // T ready

        // ---- tap GEMMs ----
        const uint32_t wtb = sb + SB_WT + (s & 1) * 20480;
        #pragma unroll
        for (int t = 0; t < 4; t++) {
            #pragma unroll
            for (int ks = 0; ks < 2; ks++) {
                uint32_t tmp[4];
                ldm4(tmp, wtb + t * 5120 + (ng * 16 + (mq & 1) * 8 + r8) * 80
                          + (mq >> 1) * 16 + ks * 32);
                uint32_t b0[2] = {tmp[0], tmp[2]};
                uint32_t b1[2] = {tmp[1], tmp[3]};
                #pragma unroll
                for (int v = 0; v < 2; v++) {
                    uint32_t av[4];
                    ldm4(av, sb + SB_T + v * 10240 + t * 2560
                             + (mg * 16 + (mq & 1) * 8 + r8) * 80
                             + (mq >> 1) * 16 + ks * 32);
                    mma16(acc[v][t][0], av, b0);
                    mma16(acc[v][t][1], av, b1);
                }
            }
        }
    }

    __syncthreads();                             // all smem reads done before reuse

    // ---------------- epilogue: inverse transform + bias/relu + mask + blend ----------------
    float* stage = (float*)(smc + SB_RAW);       // [64][65] relu(aux), local px
    const float bmv = sbm[0];

    #pragma unroll
    for (int h = 0; h < 2; h++) {
        int p = mg * 16 + r4 + 8 * h;            // pair 0..31
        float se = 0.f, so = 0.f;
        #pragma unroll
        for (int nt = 0; nt < 2; nt++)
            #pragma unroll
            for (int jj = 0; jj < 2; jj++) {
                int oc = ng * 16 + nt * 8 + 2 * c4 + jj;
                int e = h * 2 + jj;
                float bv = sbias[oc];
                float M1 = acc[0][0][nt][e], M2 = acc[0][1][nt][e];
                float M3 = acc[0][2][nt][e], M4 = acc[0][3][nt][e];
                float vme = fmaxf(M1 + M2 + M3 + bv, 0.f);
                float vmo = fmaxf(M2 - M3 - M4 + bv, 0.f);
                M1 = acc[1][0][nt][e]; M2 = acc[1][1][nt][e];
                M3 = acc[1][2][nt][e]; M4 = acc[1][3][nt][e];
                float vae = fmaxf(M1 + M2 + M3 + bv, 0.f);
                float vao = fmaxf(M2 - M3 - M4 + bv, 0.f);
                stage[(2 * p) * 65 + oc]     = vae;
                stage[(2 * p + 1) * 65 + oc] = vao;
                se += swm[oc] * vme + swm[64 + oc] * vae;
                so += swm[oc] * vmo + swm[64 + oc] * vao;
            }
        se += __shfl_xor_sync(0xffffffffu, se, 1);
        se += __shfl_xor_sync(0xffffffffu, se, 2);
        so += __shfl_xor_sync(0xffffffffu, so, 1);
        so += __shfl_xor_sync(0xffffffffu, so, 2);
        if (c4 == 0) {
            psum[ng * 64 + 2 * p]     = se;
            psum[ng * 64 + 2 * p + 1] = so;
        }
    }
    __syncthreads();

    if (tid < 64) {
        float s = psum[tid] + psum[64 + tid] + psum[128 + tid] + psum[192 + tid] + bmv;
        maskS[tid] = 1.f / (1.f + expf(-s));
    }
    __syncthreads();

    {
        int pxl = tid & 63;
        int ocg = tid >> 6;                      // 0..3 -> 16 oc each
        float mk = maskS[pxl];
        int px = hp + pxl;
        #pragma unroll 8
        for (int k = 0; k < 16; k++) {
            int oc = ocg * 16 + k;
            size_t idx = (((size_t)(b * 64 + oc)) * 128 + y) * 256 + px;
            out[idx] = m_in[idx] + mk * stage[pxl * 65 + oc];
        }
    }
}

// ---------------- launch ----------------
extern "C" void kernel_launch(void* const* d_in, const int* in_sizes, int n_in,
                              void* d_out, int out_size)
{
    const float* m  = (const float*)d_in[0];
    const float* f  = (const float*)d_in[1];
    const float* r  = (const float*)d_in[2];
    const float* bb = (const float*)d_in[3];
    const float* l  = (const float*)d_in[4];
    const float* u  = (const float*)d_in[5];
    const float* d  = (const float*)d_in[6];
    const float* wf = (const float*)d_in[7];
    const float* bf = (const float*)d_in[8];
    const float* wm = (const float*)d_in[9];
    const float* bm = (const float*)d_in[10];
    float* out = (float*)d_out;

    cudaFuncSetAttribute(fused_kernel,
                         cudaFuncAttributeMaxDynamicSharedMemorySize, SMEMB);

    prologue_kernel<<<1092, 256>>>(wf);
    nchw2xp_kernel<<<4096, 256>>>(m);
    gather_kernel<<<4096, 256>>>(bb, d, f, l, r, u);
    fused_kernel<<<2048, 256, SMEMB>>>(m, bf, wm, bm, out);
}

// round 17
// speedup vs baseline: 1.2589x; 1.2589x over previous
#include <cuda_runtime.h>
#include <cuda_fp16.h>
#include <cstdint>

#define H   128
#define W   256
#define HW  32768
#define FH  128
#define XPH 130
#define XPW 258
#define PLANE (XPH*XPW*32)

// ---------------- scratch (device globals; no allocation allowed) ----------------
__device__ __half g_xm_h[8*PLANE];   // m, padded NHWC (2x 32ch planes per batch), fp16
__device__ __half g_xa_h[8*PLANE];   // aux, same layout
__device__ __half g_wt_h[18*2048];   // weights [chunk(icc,tap)][oc64][ic32], fp16
__device__ int   g_geo[HW];
__device__ float g_dx[HW];
__device__ float g_dy[HW];

// ---------------- helpers ----------------
__device__ __forceinline__ uint32_t smem_u32(const void* p) {
    uint32_t a;
    asm("{ .reg .u64 t; cvta.to.shared.u64 t, %1; cvt.u32.u64 %0, t; }" : "=r"(a) : "l"(p));
    return a;
}
__device__ __forceinline__ uint32_t h2u(__half2 h) {
    return *reinterpret_cast<uint32_t*>(&h);
}
__device__ __forceinline__ void cp16(uint32_t dst, const void* src) {
    unsigned long long g = (unsigned long long)__cvta_generic_to_global(src);
    asm volatile("cp.async.cg.shared.global [%0], [%1], 16;" :: "r"(dst), "l"(g) : "memory");
}
__device__ __forceinline__ void ldm4(uint32_t* r, uint32_t addr) {
    asm volatile("ldmatrix.sync.aligned.m8n8.x4.shared.b16 {%0,%1,%2,%3}, [%4];"
        : "=r"(r[0]), "=r"(r[1]), "=r"(r[2]), "=r"(r[3]) : "r"(addr));
}
__device__ __forceinline__ void mma16(float* d, const uint32_t* a, const uint32_t* b) {
    asm volatile(
        "mma.sync.aligned.m16n8k16.row.col.f32.f16.f16.f32 "
        "{%0,%1,%2,%3}, {%4,%5,%6,%7}, {%8,%9}, {%0,%1,%2,%3};"
        : "+f"(d[0]), "+f"(d[1]), "+f"(d[2]), "+f"(d[3])
        : "r"(a[0]), "r"(a[1]), "r"(a[2]), "r"(a[3]), "r"(b[0]), "r"(b[1]));
}

// ---------------- 1) merged prologue: geom | pad | wtprep ----------------
__global__ __launch_bounds__(256) void prologue_kernel(const float* __restrict__ wf) {
    int t = blockIdx.x * 256 + threadIdx.x;
    if (t < 32768) {
        int p = t;
        int i = p >> 8;
        int j = p & 255;
        const float PI = 3.14159265358979323846f;
        float lat = (0.5f - (i + 0.5f) / 128.f) * PI;
        float lon = (2.f * (j + 0.5f) / 256.f - 1.f) * PI;
        float cl = cosf(lat);
        float vx = cl * sinf(lon);
        float vy = sinf(lat);
        float vz = cl * cosf(lon);
        float ax = fabsf(vx), ay = fabsf(vy), az = fabsf(vz);
        bool cond_z = (az >= ax) && (az >= ay);
        bool cond_x = (!cond_z) && (ax >= ay);
        int face;
        if (cond_z)      face = (vz > 0.f) ? 2 : 0;
        else if (cond_x) face = (vx > 0.f) ? 4 : 3;
        else             face = (vy > 0.f) ? 5 : 1;
        float den, a, bc;
        switch (face) {
            case 0: den = -vz; a = -vx / den; bc =  vy / den; break;
            case 1: den = -vy; a =  vx / den; bc = -vz / den; break;
            case 2: den =  vz; a =  vx / den; bc =  vy / den; break;
            case 3: den = -vx; a =  vz / den; bc =  vy / den; break;
            case 4: den =  vx; a = -vz / den; bc =  vy / den; break;
            default:den =  vy; a =  vx / den; bc =  vz / den; break;
        }
        float uu = fminf(fmaxf((a   + 1.f) * 0.5f * 127.f, 0.f), 127.f);
        float vv = fminf(fmaxf((1.f - bc ) * 0.5f * 127.f, 0.f), 127.f);
        int x0 = (int)floorf(uu);
        int y0 = (int)floorf(vv);
        int x1 = min(x0 + 1, 127);
        int y1 = min(y0 + 1, 127);
        g_geo[p] = face | (x0 << 3) | (y0 << 10) | (x1 << 17) | (y1 << 24);
        g_dx[p] = uu - (float)x0;
        g_dy[p] = vv - (float)y0;
    } else if (t < 230400) {
        const int PER2 = 12352;
        int tt = t - 32768;
        __half* base = (tt < 8 * PER2) ? g_xm_h : g_xa_h;
        int r = tt % (8 * PER2);
        int plane = r / PER2;
        int e = r % PER2;
        int y, x, ic2;
        if (e < 8256) {
            y = (e < 4128) ? 0 : 129;
            int o = e % 4128; x = o >> 4; ic2 = o & 15;
        } else {
            int e2 = e - 8256;
            x = (e2 < 2048) ? 0 : 257;
            int o = e2 & 2047; y = 1 + (o >> 4); ic2 = o & 15;
        }
        *(uint32_t*)(base + ((size_t)(plane * XPH + y) * XPW + x) * 32 + ic2 * 2) = 0u;
    } else if (t < 267264) {
        int idx = t - 230400;
        int ch = idx >> 11, rr = idx & 2047;
        int oc = rr >> 5, ic = rr & 31;
        int icc = ch / 9, kk = ch % 9;
        g_wt_h[idx] = __float2half(wf[(oc * 64 + icc * 32 + ic) * 9 + kk]);
    }
}

// ---------------- 2) m: NCHW -> padded NHWC fp16 ----------------
__global__ __launch_bounds__(256) void nchw2xp_kernel(const float* __restrict__ m) {
    __shared__ float sm[64][33];
    int blk = blockIdx.x;                        // b*1024 + y*8 + xt
    int xt = blk & 7, y = (blk >> 3) & 127, b = blk >> 10;
    int tid = threadIdx.x;
    int xl = tid & 31, cw = tid >> 5;
    #pragma unroll
    for (int k = 0; k < 8; k++) {
        int c = cw + k * 8;
        sm[c][xl] = m[(((size_t)(b * 64 + c)) * 128 + y) * 256 + xt * 32 + xl];
    }
    __syncthreads();
    #pragma unroll
    for (int k = 0; k < 2; k++) {
        int j = tid + k * 256;
        int px = j >> 4, c0 = (j & 15) * 4, icc = c0 >> 5;
        uint2 pk = make_uint2(h2u(__floats2half2_rn(sm[c0][px],     sm[c0 + 1][px])),
                              h2u(__floats2half2_rn(sm[c0 + 2][px], sm[c0 + 3][px])));
        *(uint2*)(g_xm_h + (((size_t)((b * 2 + icc) * XPH) + y + 1) * XPW + xt * 32 + px + 1) * 32
                  + (c0 & 31)) = pk;
    }
}

// ---------------- 3) bilinear cube gather -> padded NHWC aux fp16 ----------------
__global__ __launch_bounds__(256) void gather_kernel(
    const float* __restrict__ fb, const float* __restrict__ fd,
    const float* __restrict__ ff, const float* __restrict__ fl,
    const float* __restrict__ fr, const float* __restrict__ fu)
{
    __shared__ float sm[64][33];
    int blk = blockIdx.x;
    int xt = blk & 7, y = (blk >> 3) & 127, b = blk >> 10;
    int tid = threadIdx.x;
    int xl = tid & 31, cw = tid >> 5;
    int p = y * 256 + xt * 32 + xl;
    int geo = g_geo[p];
    int face = geo & 7;
    int x0 = (geo >> 3) & 127, y0 = (geo >> 10) & 127;
    int x1 = (geo >> 17) & 127, y1 = (geo >> 24) & 127;
    float dx = g_dx[p], dy = g_dy[p];
    float w00 = (1.f - dx) * (1.f - dy), w01 = dx * (1.f - dy);
    float w10 = (1.f - dx) * dy,         w11 = dx * dy;
    const float* fp0;
    switch (face) {
        case 0: fp0 = fb; break; case 1: fp0 = fd; break; case 2: fp0 = ff; break;
        case 3: fp0 = fl; break; case 4: fp0 = fr; break; default: fp0 = fu; break;
    }
    #pragma unroll
    for (int k = 0; k < 8; k++) {
        int c = cw + k * 8;
        const float* fp = fp0 + ((size_t)(b * 64 + c)) * (FH * FH);
        sm[c][xl] = fp[y0 * FH + x0] * w00 + fp[y0 * FH + x1] * w01
                  + fp[y1 * FH + x0] * w10 + fp[y1 * FH + x1] * w11;
    }
    __syncthreads();
    #pragma unroll
    for (int k = 0; k < 2; k++) {
        int j = tid + k * 256;
        int px = j >> 4, c0 = (j & 15) * 4, icc = c0 >> 5;
        uint2 pk = make_uint2(h2u(__floats2half2_rn(sm[c0][px],     sm[c0 + 1][px])),
                              h2u(__floats2half2_rn(sm[c0 + 2][px], sm[c0 + 3][px])));
        *(uint2*)(g_xa_h + (((size_t)((b * 2 + icc) * XPH) + y + 1) * XPW + xt * 32 + px + 1) * 32
                  + (c0 & 31)) = pk;
    }
}

// ---------------- 4) fused: both convs (mma fp16, 2-stage, 2 CTA/SM) + mask + blend ----------------
// CTA = 128 output px of one row; 256 threads, 8 warps x 16 px.
#define SB_WT  0
#define SB_ROW 30720
#define SB_PAR 72320
#define SMEMB  73664

__global__ __launch_bounds__(256) void fused_kernel(
    const float* __restrict__ m_in, const float* __restrict__ bfu,
    const float* __restrict__ wm,   const float* __restrict__ bm,
    float* __restrict__ out)
{
    extern __shared__ char smc[];
    const uint32_t sb = smem_u32(smc);
    const int tid = threadIdx.x;
    const int wid = tid >> 5;
    const int lane = tid & 31;
    const int r4 = lane >> 2, c4 = lane & 3;
    const int half = blockIdx.x & 1;
    const int y = (blockIdx.x >> 1) & 127;
    const int b = blockIdx.x >> 8;
    const int hp = half * 128;

    float* sbias = (float*)(smc + SB_PAR);
    float* swm   = (float*)(smc + SB_PAR + 256);
    float* sbm   = (float*)(smc + SB_PAR + 768);
    float* maskS = (float*)(smc + SB_PAR + 784);
    if (tid < 64)  sbias[tid] = bfu[tid];
    if (tid < 128) swm[tid]   = wm[tid];
    if (tid == 0)  sbm[0]     = bm[0];

    float acc[2][8][4];                          // [conv][nt][frag]
    #pragma unroll
    for (int v = 0; v < 2; v++)
        #pragma unroll
        for (int nt = 0; nt < 8; nt++)
            #pragma unroll
            for (int e = 0; e < 4; e++) acc[v][nt][e] = 0.f;

    auto fill = [&](int s) {
        int icc = s / 3, ky = s % 3;
        size_t rowoff = ((size_t)((b * 2 + icc) * XPH + y + ky)) * XPW * 32;
        const __half* rm = g_xm_h + rowoff;
        const __half* ra = g_xa_h + rowoff;
        uint32_t rdst = sb + SB_ROW + (s & 1) * 20800;
        uint32_t wdst = sb + SB_WT + (s & 1) * 15360;
        const __half* wsrc = g_wt_h + (icc * 9 + ky * 3) * 2048;
        #pragma unroll
        for (int i = 0; i < 8; i++) {
            int j = tid + i * 256;
            if (j < 1040) {
                int slab = (j >= 520);
                int jj = j - slab * 520;
                int px = jj >> 2, q = jj & 3;
                cp16(rdst + slab * 10400 + px * 80 + q * 16,
                     (slab ? ra : rm) + (hp + px) * 32 + q * 8);
            } else if (j < 2000) {
                int jj = j - 1040;
                int ch3 = jj / 320, rr = jj % 320;
                int oc = rr / 5, q = rr % 5;
                cp16(wdst + ch3 * 5120 + oc * 80 + q * 16,
                     wsrc + ch3 * 2048 + oc * 32 + q * 8);
            }
        }
    };

    fill(0);
    asm volatile("cp.async.commit_group;" ::: "memory");

    const int mq = lane >> 3, r8 = lane & 7;     // ldmatrix lane roles
    for (int s = 0; s < 6; s++) {
        __syncthreads();                         // prior stage's smem reads done
        if (s < 5) fill(s + 1);
        asm volatile("cp.async.commit_group;" ::: "memory");
        if (s < 5) asm volatile("cp.async.wait_group 1;" ::: "memory");
        else       asm volatile("cp.async.wait_group 0;" ::: "memory");
        __syncthreads();

        const uint32_t rowb = sb + SB_ROW + (s & 1) * 20800;
        const uint32_t wtb0 = sb + SB_WT + (s & 1) * 15360;

        #pragma unroll
        for (int kx = 0; kx < 3; kx++) {
            const uint32_t wtb = wtb0 + kx * 5120;
            #pragma unroll
            for (int ks = 0; ks < 2; ks++) {
                // A fragments first: their latency is covered by the B[0] load + MMA burst
                uint32_t am[4], aa[4];
                uint32_t aaddr = rowb + (wid * 16 + (mq & 1) * 8 + r8 + kx) * 80
                               + (mq >> 1) * 16 + ks * 32;
                ldm4(am, aaddr);
                ldm4(aa, aaddr + 10400);
                // B pairs interleaved with their MMAs: each load hides under prior pair's MMAs
                #pragma unroll
                for (int p = 0; p < 4; p++) {
                    uint32_t tb[4];
                    ldm4(tb, wtb + ((p * 2 + (mq >> 1)) * 8 + r8) * 80
                             + (mq & 1) * 16 + ks * 32);
                    uint32_t b0[2] = {tb[0], tb[1]};
                    uint32_t b1[2] = {tb[2], tb[3]};
                    mma16(acc[0][2 * p],     am, b0);
                    mma16(acc[1][2 * p],     aa, b0);
                    mma16(acc[0][2 * p + 1], am, b1);
                    mma16(acc[1][2 * p + 1], aa, b1);
                }
            }
        }
    }

    __syncthreads();                             // all MMA smem reads done before stage reuse

    // ---------------- epilogue ----------------
    float* stage = (float*)(smc + SB_ROW);       // [128][65] relu(aux), local px
    const float bmv = sbm[0];
    const int px0 = wid * 16 + r4;

    float tot[2];
    #pragma unroll
    for (int h = 0; h < 2; h++) {
        float s = 0.f;
        int px = px0 + 8 * h;
        #pragma unroll
        for (int nt = 0; nt < 8; nt++)
            #pragma unroll
            for (int j = 0; j < 2; j++) {
                int oc = nt * 8 + 2 * c4 + j;
                float bv = sbias[oc];
                float vm = fmaxf(acc[0][nt][2 * h + j] + bv, 0.f);
                float va = fmaxf(acc[1][nt][2 * h + j] + bv, 0.f);
                s += swm[oc] * vm + swm[64 + oc] * va;
                stage[px * 65 + oc] = va;
            }
        tot[h] = s;
    }
    #pragma unroll
    for (int h = 0; h < 2; h++) {
        float s = tot[h];
        s += __shfl_xor_sync(0xffffffffu, s, 1);
        s += __shfl_xor_sync(0xffffffffu, s, 2);
        if (c4 == 0)
            maskS[px0 + 8 * h] = 1.f / (1.f + expf(-(s + bmv)));
    }
    __syncthreads();

    {
        int pxl = tid & 127;
        int ocg = tid >> 7;                      // 0/1 -> oc 0..31 / 32..63
        float mk = maskS[pxl];
        int px = hp + pxl;
        #pragma unroll 8
        for (int k = 0; k < 32; k++) {
            int oc = ocg * 32 + k;
            size_t idx = (((size_t)(b * 64 + oc)) * 128 + y) * 256 + px;
            out[idx] = m_in[idx] + mk * stage[pxl * 65 + oc];
        }
    }
}

// ---------------- launch ----------------
extern "C" void kernel_launch(void* const* d_in, const int* in_sizes, int n_in,
                              void* d_out, int out_size)
{
    const float* m  = (const float*)d_in[0];
    const float* f  = (const float*)d_in[1];
    const float* r  = (const float*)d_in[2];
    const float* bb = (const float*)d_in[3];
    const float* l  = (const float*)d_in[4];
    const float* u  = (const float*)d_in[5];
    const float* d  = (const float*)d_in[6];
    const float* wf = (const float*)d_in[7];
    const float* bf = (const float*)d_in[8];
    const float* wm = (const float*)d_in[9];
    const float* bm = (const float*)d_in[10];
    float* out = (float*)d_out;

    cudaFuncSetAttribute(fused_kernel,
                         cudaFuncAttributeMaxDynamicSharedMemorySize, SMEMB);

    prologue_kernel<<<1044, 256>>>(wf);
    nchw2xp_kernel<<<4096, 256>>>(m);
    gather_kernel<<<4096, 256>>>(bb, d, f, l, r, u);
    fused_kernel<<<1024, 256, SMEMB>>>(m, bf, wm, bm, out);
}